// round 14
// baseline (speedup 1.0000x reference)
#include <cuda_runtime.h>
#include <cstdint>
#include <cstddef>

// MyLoc1d: out[b,o,p] = scale * sum_{c,f} x[b,c,p+f] * filt[o,c,p,f]
// x:    (32, 128, 1024)  f32   d_in[0]
// filt: (128, 128, 1017, 8) f32 d_in[1]
// out:  (32, 128, 1017)  f32
// scale = 1/sqrt(128*8) = 1/32 exactly.
//
// One block per patch p: GEMM M=32(b) x N=128(o) x K=1024(c*8+f).
// K in 16 chunks of 64 (8 channels), double-buffered cp.async.
// Packed fma.rn.f32x2 over adjacent-k pairs.
// Warp-level tiling: warp w owns a 32-o x 16-b sub-tile (wo=w&3, wb=w>>2)
// so each wv LDS.128 touches only 8 distinct addresses (1 crossbar cycle)
// instead of 32 — kills the 16x cross-warp filter-tile duplication that
// would otherwise make the crossbar the binding pipe.

#define NUM_P 1017

static constexpr int WS_STRIDE = 68;                 // floats; 272B = 17*16B
static constexpr int WS_FLOATS = 128 * WS_STRIDE;    // 8704
static constexpr int XS_FLOATS = 32 * WS_STRIDE;     // 2176
static constexpr int BUF_FLOATS = WS_FLOATS + XS_FLOATS; // 10880
static constexpr int SMEM_BYTES = 2 * BUF_FLOATS * 4;    // 87040

__device__ __forceinline__ void cp_async16(uint32_t s, const void* g) {
    asm volatile("cp.async.cg.shared.global [%0], [%1], 16;\n" :: "r"(s), "l"(g));
}
__device__ __forceinline__ void cp_async4(uint32_t s, const void* g) {
    asm volatile("cp.async.ca.shared.global [%0], [%1], 4;\n" :: "r"(s), "l"(g));
}

__global__ void __launch_bounds__(256, 2)
loc1d_kernel(const float* __restrict__ x,
             const float* __restrict__ w,
             float* __restrict__ out)
{
    extern __shared__ float smem[];
    const int p    = blockIdx.x;      // 0..1016
    const int t    = threadIdx.x;     // 0..255
    const int warp = t >> 5;          // 0..7
    const int lane = t & 31;

    // warp sub-tile: 32 o x 16 b
    const int wo = warp & 3;          // o-range [wo*32, wo*32+32)
    const int wb = warp >> 2;         // b-range [wb*16, wb*16+16)
    const int ol = lane & 7;          // thread o = wo*32 + ol + 8j
    const int bl = lane >> 3;         // thread b = wb*16 + bl + 4i

    const int o_base = wo * 32 + ol;
    const int b_base = wb * 16 + bl;

    const uint32_t smem_u = (uint32_t)__cvta_generic_to_shared(smem);

    // ---- async load of one K-chunk (8 channels) into buffer buf ----
    auto issue = [&](int chunk, int buf) {
        const int c0 = chunk * 8;
        const uint32_t ws_u = smem_u + (uint32_t)buf * (BUF_FLOATS * 4);
        const uint32_t xs_u = ws_u + WS_FLOATS * 4;

        // filt tile: 128 o x 8 c x 8 f = 2048 float4; 8 per thread.
        #pragma unroll
        for (int i = 0; i < 8; ++i) {
            int q   = t + i * 256;        // 0..2047
            int row = q >> 1;             // (o, cl)
            int h   = q & 1;
            int o   = row >> 3;
            int cl  = row & 7;
            const float* g = w + ((((size_t)o * 128 + (size_t)(c0 + cl)) * NUM_P + p) * 8 + h * 4);
            cp_async16(ws_u + (uint32_t)(o * WS_STRIDE + cl * 8 + h * 4) * 4, g);
        }
        // x tile: 32 b x 8 c x 8 f; 8 scalars per thread.
        {
            int b  = t >> 3;
            int cl = t & 7;
            const float* g = x + (((size_t)b * 128 + (size_t)(c0 + cl)) * 1024 + p);
            uint32_t s = xs_u + (uint32_t)(b * WS_STRIDE + cl * 8) * 4;
            #pragma unroll
            for (int f = 0; f < 8; ++f) cp_async4(s + f * 4, g + f);
        }
        asm volatile("cp.async.commit_group;\n" ::: "memory");
    };

    // accumulators: 4b x 4o, each a packed f32x2 partial pair over even/odd k
    unsigned long long acc[4][4];
    #pragma unroll
    for (int i = 0; i < 4; ++i)
        #pragma unroll
        for (int j = 0; j < 4; ++j) acc[i][j] = 0ull;

    issue(0, 0);

    for (int chunk = 0; chunk < 16; ++chunk) {
        if (chunk + 1 < 16) {
            issue(chunk + 1, (chunk + 1) & 1);
            asm volatile("cp.async.wait_group 1;\n" ::: "memory");
        } else {
            asm volatile("cp.async.wait_group 0;\n" ::: "memory");
        }
        __syncthreads();

        const float* wsb = smem + (size_t)(chunk & 1) * BUF_FLOATS;
        const float* xsb = wsb + WS_FLOATS;

        #pragma unroll 4
        for (int kk = 0; kk < 16; ++kk) {       // 4 k per step
            ulonglong2 wv[4], xv[4];
            #pragma unroll
            for (int j = 0; j < 4; ++j)
                wv[j] = *reinterpret_cast<const ulonglong2*>(
                            wsb + (size_t)(o_base + 8 * j) * WS_STRIDE + kk * 4);
            #pragma unroll
            for (int i = 0; i < 4; ++i)
                xv[i] = *reinterpret_cast<const ulonglong2*>(
                            xsb + (size_t)(b_base + 4 * i) * WS_STRIDE + kk * 4);

            #pragma unroll
            for (int i = 0; i < 4; ++i)
                #pragma unroll
                for (int j = 0; j < 4; ++j) {
                    asm("fma.rn.f32x2 %0, %1, %2, %0;"
                        : "+l"(acc[i][j]) : "l"(xv[i].x), "l"(wv[j].x));
                    asm("fma.rn.f32x2 %0, %1, %2, %0;"
                        : "+l"(acc[i][j]) : "l"(xv[i].y), "l"(wv[j].y));
                }
        }
        __syncthreads();
    }

    // ---- epilogue ----
    const float scale = 0.03125f;   // (128*8)^-0.5
    #pragma unroll
    for (int i = 0; i < 4; ++i) {
        int b = b_base + 4 * i;
        #pragma unroll
        for (int j = 0; j < 4; ++j) {
            int o = o_base + 8 * j;
            float2 v = *reinterpret_cast<float2*>(&acc[i][j]);
            out[((size_t)b * 128 + o) * NUM_P + p] = (v.x + v.y) * scale;
        }
    }
}

extern "C" void kernel_launch(void* const* d_in, const int* in_sizes, int n_in,
                              void* d_out, int out_size)
{
    const float* x = (const float*)d_in[0];   // (32,128,1024)
    const float* w = (const float*)d_in[1];   // (128,128,1017,8)
    float* out = (float*)d_out;               // (32,128,1017)

    cudaFuncSetAttribute(loc1d_kernel,
                         cudaFuncAttributeMaxDynamicSharedMemorySize, SMEM_BYTES);
    loc1d_kernel<<<NUM_P, 256, SMEM_BYTES>>>(x, w, out);
}

// round 16
// speedup vs baseline: 1.1838x; 1.1838x over previous
#include <cuda_runtime.h>
#include <cstdint>
#include <cstddef>

// MyLoc1d: out[b,o,p] = scale * sum_{c,f} x[b,c,p+f] * filt[o,c,p,f]
// R14 fix: x-loader lane remap (f-major). Old mapping put every lane of a
// cp.async4 in a different 128B line (32 L1 wavefronts/instr, 2048/CTA/chunk,
// measured L1=71.7% binding). New mapping: lanes cover 8 contiguous f x 4
// (b,c) rows -> 4-8 lines/instr (~256-512 wavefronts), smem write side is one
// contiguous 128B segment per warp.

#define NUM_P 1017

static constexpr int WS_STRIDE = 68;                 // floats; 272B = 17*16B
static constexpr int WS_FLOATS = 128 * WS_STRIDE;    // 8704
static constexpr int XS_FLOATS = 32 * WS_STRIDE;     // 2176
static constexpr int BUF_FLOATS = WS_FLOATS + XS_FLOATS; // 10880
static constexpr int SMEM_BYTES = 2 * BUF_FLOATS * 4;    // 87040

__device__ __forceinline__ void cp_async16(uint32_t s, const void* g) {
    asm volatile("cp.async.cg.shared.global [%0], [%1], 16;\n" :: "r"(s), "l"(g));
}
__device__ __forceinline__ void cp_async4(uint32_t s, const void* g) {
    asm volatile("cp.async.ca.shared.global [%0], [%1], 4;\n" :: "r"(s), "l"(g));
}

__global__ void __launch_bounds__(256, 2)
loc1d_kernel(const float* __restrict__ x,
             const float* __restrict__ w,
             float* __restrict__ out)
{
    extern __shared__ float smem[];
    const int p    = blockIdx.x;      // 0..1016
    const int t    = threadIdx.x;     // 0..255
    const int warp = t >> 5;          // 0..7
    const int lane = t & 31;

    // warp sub-tile: 32 o x 16 b
    const int wo = warp & 3;
    const int wb = warp >> 2;
    const int ol = lane & 7;
    const int bl = lane >> 3;

    const int o_base = wo * 32 + ol;
    const int b_base = wb * 16 + bl;

    // x-loader decomposition (f-major for coalescing)
    const int xf  = t & 7;            // filter tap 0..7
    const int xcl = (t >> 3) & 7;     // channel-in-chunk 0..7
    const int xb0 = t >> 6;           // base batch 0..3 (b = xb0 + 4i)

    const uint32_t smem_u = (uint32_t)__cvta_generic_to_shared(smem);

    auto issue = [&](int chunk, int buf) {
        const int c0 = chunk * 8;
        const uint32_t ws_u = smem_u + (uint32_t)buf * (BUF_FLOATS * 4);
        const uint32_t xs_u = ws_u + WS_FLOATS * 4;

        // filt tile: 128 o x 8 c x 8 f = 2048 float4; 8 per thread.
        #pragma unroll
        for (int i = 0; i < 8; ++i) {
            int q   = t + i * 256;
            int row = q >> 1;
            int h   = q & 1;
            int o   = row >> 3;
            int cl  = row & 7;
            const float* g = w + ((((size_t)o * 128 + (size_t)(c0 + cl)) * NUM_P + p) * 8 + h * 4);
            cp_async16(ws_u + (uint32_t)(o * WS_STRIDE + cl * 8 + h * 4) * 4, g);
        }
        // x tile: 32 b x 8 c x 8 f. f-major lane map: warp lanes span 8 f x 4 cl
        // (single b) -> few distinct 128B lines per instruction.
        #pragma unroll
        for (int i = 0; i < 8; ++i) {
            int b = xb0 + 4 * i;      // covers b 0..31 across (xb0, i)
            const float* g = x + (((size_t)b * 128 + (size_t)(c0 + xcl)) * 1024 + p + xf);
            cp_async4(xs_u + (uint32_t)(b * WS_STRIDE + xcl * 8 + xf) * 4, g);
        }
        asm volatile("cp.async.commit_group;\n" ::: "memory");
    };

    unsigned long long acc[4][4];
    #pragma unroll
    for (int i = 0; i < 4; ++i)
        #pragma unroll
        for (int j = 0; j < 4; ++j) acc[i][j] = 0ull;

    issue(0, 0);

    for (int chunk = 0; chunk < 16; ++chunk) {
        if (chunk + 1 < 16) {
            issue(chunk + 1, (chunk + 1) & 1);
            asm volatile("cp.async.wait_group 1;\n" ::: "memory");
        } else {
            asm volatile("cp.async.wait_group 0;\n" ::: "memory");
        }
        __syncthreads();

        const float* wsb = smem + (size_t)(chunk & 1) * BUF_FLOATS;
        const float* xsb = wsb + WS_FLOATS;

        #pragma unroll 4
        for (int kk = 0; kk < 16; ++kk) {
            ulonglong2 wv[4], xv[4];
            #pragma unroll
            for (int j = 0; j < 4; ++j)
                wv[j] = *reinterpret_cast<const ulonglong2*>(
                            wsb + (size_t)(o_base + 8 * j) * WS_STRIDE + kk * 4);
            #pragma unroll
            for (int i = 0; i < 4; ++i)
                xv[i] = *reinterpret_cast<const ulonglong2*>(
                            xsb + (size_t)(b_base + 4 * i) * WS_STRIDE + kk * 4);

            #pragma unroll
            for (int i = 0; i < 4; ++i)
                #pragma unroll
                for (int j = 0; j < 4; ++j) {
                    asm("fma.rn.f32x2 %0, %1, %2, %0;"
                        : "+l"(acc[i][j]) : "l"(xv[i].x), "l"(wv[j].x));
                    asm("fma.rn.f32x2 %0, %1, %2, %0;"
                        : "+l"(acc[i][j]) : "l"(xv[i].y), "l"(wv[j].y));
                }
        }
        __syncthreads();
    }

    const float scale = 0.03125f;   // (128*8)^-0.5
    #pragma unroll
    for (int i = 0; i < 4; ++i) {
        int b = b_base + 4 * i;
        #pragma unroll
        for (int j = 0; j < 4; ++j) {
            int o = o_base + 8 * j;
            float2 v = *reinterpret_cast<float2*>(&acc[i][j]);
            out[((size_t)b * 128 + o) * NUM_P + p] = (v.x + v.y) * scale;
        }
    }
}

extern "C" void kernel_launch(void* const* d_in, const int* in_sizes, int n_in,
                              void* d_out, int out_size)
{
    const float* x = (const float*)d_in[0];
    const float* w = (const float*)d_in[1];
    float* out = (float*)d_out;

    cudaFuncSetAttribute(loc1d_kernel,
                         cudaFuncAttributeMaxDynamicSharedMemorySize, SMEM_BYTES);
    loc1d_kernel<<<NUM_P, 256, SMEM_BYTES>>>(x, w, out);
}